// round 5
// baseline (speedup 1.0000x reference)
#include <cuda_runtime.h>
#include <math.h>

#define BB 64
#define LL 2048
#define DD 128
#define KK 64
#define TU 192   // 3*K2

// ---------------- scratch (no cudaMalloc allowed) ----------------
__device__ float g_tok  [BB*LL*DD];   // [B,L,128] gathered embeddings
__device__ float g_xproj[BB*LL*TU];   // [B,L,192] tok@Wx + b0
__device__ float g_L1   [BB*LL*KK];   // conv1+relu
__device__ float g_Lfeat[BB*LL*KK];   // normalized attention features
__device__ float g_hT   [BB*KK];      // GRU final state

// ---------------- helpers ----------------
__device__ __forceinline__ float sigm_f(float x){
    x = fminf(fmaxf(x, -30.f), 30.f);
    return __fdividef(1.f, 1.f + __expf(-x));
}
__device__ __forceinline__ float tanh_f(float x){
    x = fminf(fmaxf(x, -15.f), 15.f);
    float e = __expf(-2.f * x);
    return __fdividef(1.f - e, 1.f + e);
}
__device__ __forceinline__ void ffma2(unsigned long long &acc,
                                      unsigned long long a,
                                      unsigned long long b){
    asm("fma.rn.f32x2 %0, %1, %2, %0;" : "+l"(acc) : "l"(a), "l"(b));
}
__device__ __forceinline__ unsigned long long pack2(float x, float y){
    unsigned long long r;
    asm("mov.b64 %0, {%1, %2};" : "=l"(r) : "f"(x), "f"(y));
    return r;
}
__device__ __forceinline__ float2 unpack2(unsigned long long v){
    float2 f;
    asm("mov.b64 {%0, %1}, %2;" : "=f"(f.x), "=f"(f.y) : "l"(v));
    return f;
}

// ---------------- k0: gather embeddings ----------------
__global__ void __launch_bounds__(256) k_gather(const int* __restrict__ code,
                                                const float4* __restrict__ E4){
    int i = blockIdx.x * 256 + threadIdx.x;   // over BB*LL*32 float4s
    int token = i >> 5;
    int j = i & 31;
    int row = __ldg(&code[token]);
    ((float4*)g_tok)[i] = E4[row * 32 + j];
}

// ---------------- k1: x_proj = tok @ Wx + b0  (M=B*L, N=192, K=128) ----------------
__global__ void __launch_bounds__(256) k_xproj(const float* __restrict__ Wx,
                                               const float* __restrict__ bg){
    __shared__ __align__(16) float As[64 * 36];
    __shared__ __align__(16) float Bs[32 * 192];
    int tid = threadIdx.x;
    int tx = tid & 15, ty = tid >> 4;
    int r0 = ty * 4;
    int rowbase = blockIdx.x * 64;

    float4 acc[4][3];
    #pragma unroll
    for (int i = 0; i < 4; i++)
        #pragma unroll
        for (int j = 0; j < 3; j++)
            acc[i][j] = make_float4(0.f, 0.f, 0.f, 0.f);

    const float4* tok4 = (const float4*)g_tok;
    const float4* Wx4  = (const float4*)Wx;

    for (int kt = 0; kt < 4; kt++){
        __syncthreads();
        #pragma unroll
        for (int v = 0; v < 2; v++){
            int q = tid + v * 256;
            int row = q >> 3, j = q & 7;
            ((float4*)As)[row * 9 + j] = tok4[(rowbase + row) * 32 + kt * 8 + j];
        }
        #pragma unroll
        for (int v = 0; v < 6; v++){
            int q = tid + v * 256;
            ((float4*)Bs)[q] = Wx4[kt * 1536 + q];
        }
        __syncthreads();
        #pragma unroll
        for (int kk = 0; kk < 32; kk++){
            float a[4];
            #pragma unroll
            for (int i = 0; i < 4; i++) a[i] = As[(r0 + i) * 36 + kk];
            float4 b0 = ((const float4*)Bs)[kk * 48 + tx * 3 + 0];
            float4 b1 = ((const float4*)Bs)[kk * 48 + tx * 3 + 1];
            float4 b2 = ((const float4*)Bs)[kk * 48 + tx * 3 + 2];
            #pragma unroll
            for (int i = 0; i < 4; i++){
                acc[i][0].x = fmaf(a[i], b0.x, acc[i][0].x);
                acc[i][0].y = fmaf(a[i], b0.y, acc[i][0].y);
                acc[i][0].z = fmaf(a[i], b0.z, acc[i][0].z);
                acc[i][0].w = fmaf(a[i], b0.w, acc[i][0].w);
                acc[i][1].x = fmaf(a[i], b1.x, acc[i][1].x);
                acc[i][1].y = fmaf(a[i], b1.y, acc[i][1].y);
                acc[i][1].z = fmaf(a[i], b1.z, acc[i][1].z);
                acc[i][1].w = fmaf(a[i], b1.w, acc[i][1].w);
                acc[i][2].x = fmaf(a[i], b2.x, acc[i][2].x);
                acc[i][2].y = fmaf(a[i], b2.y, acc[i][2].y);
                acc[i][2].z = fmaf(a[i], b2.z, acc[i][2].z);
                acc[i][2].w = fmaf(a[i], b2.w, acc[i][2].w);
            }
        }
    }
    const float4* bg4 = (const float4*)bg;
    #pragma unroll
    for (int i = 0; i < 4; i++){
        int row = rowbase + r0 + i;
        float4* o = ((float4*)g_xproj) + row * 48 + tx * 3;
        #pragma unroll
        for (int j = 0; j < 3; j++){
            float4 bb = bg4[tx * 3 + j];
            float4 v = acc[i][j];
            v.x += bb.x; v.y += bb.y; v.z += bb.z; v.w += bb.w;
            o[j] = v;
        }
    }
}

// ---------------- k2: conv1 (+bias +relu), K = 8*128 ----------------
__global__ void __launch_bounds__(256) k_conv1(const float* __restrict__ w,
                                               const float* __restrict__ bias){
    __shared__ __align__(16) float Xs[71 * 68];
    __shared__ __align__(16) float Ws[64 * 64];
    int b = blockIdx.y;
    int l0 = blockIdx.x * 64;
    int tid = threadIdx.x, tx = tid & 15, ty = tid >> 4;
    int r0 = ty * 4;

    float4 acc[4];
    #pragma unroll
    for (int i = 0; i < 4; i++) acc[i] = make_float4(0.f, 0.f, 0.f, 0.f);

    const float4* src4 = (const float4*)g_tok;

    for (int h = 0; h < 2; h++){
        __syncthreads();
        for (int q = tid; q < 71 * 16; q += 256){
            int row = q >> 4, j = q & 15;
            int l = l0 - 3 + row;
            float4 v = make_float4(0.f, 0.f, 0.f, 0.f);
            if (l >= 0 && l < LL) v = src4[(b * LL + l) * 32 + h * 16 + j];
            ((float4*)Xs)[row * 17 + j] = v;
        }
        for (int ww = 0; ww < 8; ww++){
            __syncthreads();
            const float4* slab4 = (const float4*)(w + (ww * 128 + h * 64) * 64);
            for (int q = tid; q < 1024; q += 256) ((float4*)Ws)[q] = slab4[q];
            __syncthreads();
            #pragma unroll
            for (int ci = 0; ci < 64; ci++){
                float4 bb = ((const float4*)Ws)[ci * 16 + tx];
                float a0 = Xs[(r0 + 0 + ww) * 68 + ci];
                float a1 = Xs[(r0 + 1 + ww) * 68 + ci];
                float a2 = Xs[(r0 + 2 + ww) * 68 + ci];
                float a3 = Xs[(r0 + 3 + ww) * 68 + ci];
                acc[0].x = fmaf(a0, bb.x, acc[0].x); acc[0].y = fmaf(a0, bb.y, acc[0].y);
                acc[0].z = fmaf(a0, bb.z, acc[0].z); acc[0].w = fmaf(a0, bb.w, acc[0].w);
                acc[1].x = fmaf(a1, bb.x, acc[1].x); acc[1].y = fmaf(a1, bb.y, acc[1].y);
                acc[1].z = fmaf(a1, bb.z, acc[1].z); acc[1].w = fmaf(a1, bb.w, acc[1].w);
                acc[2].x = fmaf(a2, bb.x, acc[2].x); acc[2].y = fmaf(a2, bb.y, acc[2].y);
                acc[2].z = fmaf(a2, bb.z, acc[2].z); acc[2].w = fmaf(a2, bb.w, acc[2].w);
                acc[3].x = fmaf(a3, bb.x, acc[3].x); acc[3].y = fmaf(a3, bb.y, acc[3].y);
                acc[3].z = fmaf(a3, bb.z, acc[3].z); acc[3].w = fmaf(a3, bb.w, acc[3].w);
            }
        }
    }
    float4 cbv = ((const float4*)bias)[tx];
    #pragma unroll
    for (int i = 0; i < 4; i++){
        float4 v = acc[i];
        v.x = fmaxf(v.x + cbv.x, 0.f); v.y = fmaxf(v.y + cbv.y, 0.f);
        v.z = fmaxf(v.z + cbv.z, 0.f); v.w = fmaxf(v.w + cbv.w, 0.f);
        ((float4*)g_L1)[(b * LL + l0 + r0 + i) * 16 + tx] = v;
    }
}

// ---------------- k3: GRU scan, one block per batch (f32x2 + 2-step prefetch) ----------------
__global__ void __launch_bounds__(192) k_gru(const float* __restrict__ Wh,
                                             const float* __restrict__ bg){
    int b = blockIdx.x, t = threadIdx.x;        // t in [0,192)
    __shared__ __align__(16) float h_sh[64];
    __shared__ float hp_sh[192];

    unsigned long long wh2[32];
    #pragma unroll
    for (int j = 0; j < 32; j++)
        wh2[j] = pack2(Wh[(2*j) * 192 + t], Wh[(2*j+1) * 192 + t]);
    float b1 = bg[192 + t];
    if (t < 64) h_sh[t] = 0.f;
    __syncthreads();

    const float* xb = g_xproj + b * LL * 192;
    // two-deep x_proj prefetch registers (DRAM latency > one step)
    float xz0 = 0.f, xr0 = 0.f, xh0 = 0.f;
    float xz1 = 0.f, xr1 = 0.f, xh1 = 0.f;
    float hn = 0.f;
    if (t < 64){
        xz0 = xb[t];            xr0 = xb[64 + t];            xh0 = xb[128 + t];
        xz1 = xb[192 + t];      xr1 = xb[192 + 64 + t];      xh1 = xb[192 + 128 + t];
    }

    for (int l = 0; l < LL; l++){
        // matvec: all 192 threads compute hp[t] = Wh[:,t]·h + b1
        {
            unsigned long long a0 = 0ull, a1 = 0ull, a2 = 0ull, a3 = 0ull;
            const ulonglong2* h2 = (const ulonglong2*)h_sh;
            #pragma unroll
            for (int k = 0; k < 16; k++){
                ulonglong2 hv = h2[k];
                if ((k & 1) == 0){ ffma2(a0, wh2[2*k], hv.x); ffma2(a1, wh2[2*k+1], hv.y); }
                else             { ffma2(a2, wh2[2*k], hv.x); ffma2(a3, wh2[2*k+1], hv.y); }
            }
            float2 f0 = unpack2(a0), f1 = unpack2(a1), f2 = unpack2(a2), f3 = unpack2(a3);
            hp_sh[t] = ((f0.x + f0.y) + (f1.x + f1.y))
                     + ((f2.x + f2.y) + (f3.x + f3.y)) + b1;
        }
        __syncthreads();
        if (t < 64){
            // issue prefetch for l+2 immediately (lands in ~2 steps)
            int lp = (l + 2 < LL) ? (l + 2) : (LL - 1);
            float pz = xb[lp * 192 + t];
            float pr = xb[lp * 192 + 64 + t];
            float ph = xb[lp * 192 + 128 + t];

            float z  = sigm_f(xz0 + hp_sh[t]);
            float r  = sigm_f(xr0 + hp_sh[64 + t]);
            float hh = tanh_f(xh0 + r * hp_sh[128 + t]);
            hn = fmaf(z, hn - hh, hh);           // z*h + (1-z)*hh
            h_sh[t] = hn;

            xz0 = xz1; xr0 = xr1; xh0 = xh1;
            xz1 = pz;  xr1 = pr;  xh1 = ph;
        }
        __syncthreads();
    }
    if (t < 64) g_hT[b * 64 + t] = hn;
}

// ---------------- k4: conv2 + bias, * h_T, l2-normalize ----------------
__global__ void __launch_bounds__(256) k_conv2(const float* __restrict__ w,
                                               const float* __restrict__ bias){
    __shared__ __align__(16) float Xs[71 * 68];
    __shared__ __align__(16) float Ws[64 * 64];
    __shared__ float inv[64];
    int b = blockIdx.y;
    int l0 = blockIdx.x * 64;
    int tid = threadIdx.x, tx = tid & 15, ty = tid >> 4;
    int r0 = ty * 4;

    float4 acc[4];
    #pragma unroll
    for (int i = 0; i < 4; i++) acc[i] = make_float4(0.f, 0.f, 0.f, 0.f);

    const float4* src4 = (const float4*)g_L1;
    for (int q = tid; q < 71 * 16; q += 256){
        int row = q >> 4, j = q & 15;
        int l = l0 - 3 + row;
        float4 v = make_float4(0.f, 0.f, 0.f, 0.f);
        if (l >= 0 && l < LL) v = src4[(b * LL + l) * 16 + j];
        ((float4*)Xs)[row * 17 + j] = v;
    }
    for (int ww = 0; ww < 8; ww++){
        __syncthreads();
        const float4* slab4 = (const float4*)(w + ww * 64 * 64);
        for (int q = tid; q < 1024; q += 256) ((float4*)Ws)[q] = slab4[q];
        __syncthreads();
        #pragma unroll
        for (int ci = 0; ci < 64; ci++){
            float4 bb = ((const float4*)Ws)[ci * 16 + tx];
            float a0 = Xs[(r0 + 0 + ww) * 68 + ci];
            float a1 = Xs[(r0 + 1 + ww) * 68 + ci];
            float a2 = Xs[(r0 + 2 + ww) * 68 + ci];
            float a3 = Xs[(r0 + 3 + ww) * 68 + ci];
            acc[0].x = fmaf(a0, bb.x, acc[0].x); acc[0].y = fmaf(a0, bb.y, acc[0].y);
            acc[0].z = fmaf(a0, bb.z, acc[0].z); acc[0].w = fmaf(a0, bb.w, acc[0].w);
            acc[1].x = fmaf(a1, bb.x, acc[1].x); acc[1].y = fmaf(a1, bb.y, acc[1].y);
            acc[1].z = fmaf(a1, bb.z, acc[1].z); acc[1].w = fmaf(a1, bb.w, acc[1].w);
            acc[2].x = fmaf(a2, bb.x, acc[2].x); acc[2].y = fmaf(a2, bb.y, acc[2].y);
            acc[2].z = fmaf(a2, bb.z, acc[2].z); acc[2].w = fmaf(a2, bb.w, acc[2].w);
            acc[3].x = fmaf(a3, bb.x, acc[3].x); acc[3].y = fmaf(a3, bb.y, acc[3].y);
            acc[3].z = fmaf(a3, bb.z, acc[3].z); acc[3].w = fmaf(a3, bb.w, acc[3].w);
        }
    }
    float4 cb = ((const float4*)bias)[tx];
    float4 ht = ((const float4*)g_hT)[b * 16 + tx];
    float4 val[4];
    #pragma unroll
    for (int i = 0; i < 4; i++){
        val[i].x = (acc[i].x + cb.x) * ht.x;
        val[i].y = (acc[i].y + cb.y) * ht.y;
        val[i].z = (acc[i].z + cb.z) * ht.z;
        val[i].w = (acc[i].w + cb.w) * ht.w;
    }
    __syncthreads();
    #pragma unroll
    for (int i = 0; i < 4; i++)
        ((float4*)Xs)[(r0 + i) * 17 + tx] = val[i];
    __syncthreads();
    if (tid < 64){
        float s = 0.f;
        #pragma unroll
        for (int c = 0; c < 64; c++){
            float v = Xs[tid * 68 + c];
            s = fmaf(v, v, s);
        }
        inv[tid] = rsqrtf(s + 1e-12f);
    }
    __syncthreads();
    #pragma unroll
    for (int i = 0; i < 4; i++){
        float iv = inv[r0 + i];
        float4 v = val[i];
        v.x *= iv; v.y *= iv; v.z *= iv; v.w *= iv;
        ((float4*)g_Lfeat)[(b * LL + l0 + r0 + i) * 16 + tx] = v;
    }
}

// ---------------- k5: conv3 -> softmax -> n_hat -> logits -> softmax ----------------
__device__ __forceinline__ float blockMax256(float v, float* red){
    #pragma unroll
    for (int o = 16; o; o >>= 1) v = fmaxf(v, __shfl_xor_sync(0xffffffffu, v, o));
    if ((threadIdx.x & 31) == 0) red[threadIdx.x >> 5] = v;
    __syncthreads();
    if (threadIdx.x < 32){
        float u = (threadIdx.x < 8) ? red[threadIdx.x] : -3.4e38f;
        #pragma unroll
        for (int o = 4; o; o >>= 1) u = fmaxf(u, __shfl_xor_sync(0xffffffffu, u, o));
        if (threadIdx.x == 0) red[0] = u;
    }
    __syncthreads();
    float r = red[0];
    __syncthreads();
    return r;
}
__device__ __forceinline__ float blockSum256(float v, float* red){
    #pragma unroll
    for (int o = 16; o; o >>= 1) v += __shfl_xor_sync(0xffffffffu, v, o);
    if ((threadIdx.x & 31) == 0) red[threadIdx.x >> 5] = v;
    __syncthreads();
    if (threadIdx.x < 32){
        float u = (threadIdx.x < 8) ? red[threadIdx.x] : 0.f;
        #pragma unroll
        for (int o = 4; o; o >>= 1) u += __shfl_xor_sync(0xffffffffu, u, o);
        if (threadIdx.x == 0) red[0] = u;
    }
    __syncthreads();
    float r = red[0];
    __syncthreads();
    return r;
}

__global__ void __launch_bounds__(256) k_final(const int* __restrict__ code,
                                               const float* __restrict__ bias_tb,
                                               const float* __restrict__ c3w,
                                               const float* __restrict__ c3b,
                                               float* __restrict__ out){
    __shared__ __align__(16) float alpha[2048];
    __shared__ __align__(16) float Xt[135 * 68];
    __shared__ __align__(16) float w3s[512];
    __shared__ __align__(16) float nh[128];
    __shared__ float red[32];
    int b = blockIdx.x, tid = threadIdx.x;

    for (int q = tid; q < 512; q += 256) w3s[q] = c3w[q];
    float c3bv = __ldg(c3b);

    const float4* lf4 = (const float4*)g_Lfeat;
    for (int t16 = 0; t16 < 16; t16++){
        int l0 = t16 * 128;
        __syncthreads();
        for (int q = tid; q < 135 * 16; q += 256){
            int row = q >> 4, j = q & 15;
            int l = l0 - 3 + row;
            float4 v = make_float4(0.f, 0.f, 0.f, 0.f);
            if (l >= 0 && l < LL) v = lf4[(b * LL + l) * 16 + j];
            ((float4*)Xt)[row * 17 + j] = v;
        }
        __syncthreads();
        if (tid < 128){
            int li = tid;
            float s0 = c3bv, s1 = 0.f, s2 = 0.f, s3 = 0.f;
            #pragma unroll
            for (int ww = 0; ww < 8; ww++){
                const float4* xr = ((const float4*)Xt) + (li + ww) * 17;
                const float4* wr = ((const float4*)w3s) + ww * 16;
                #pragma unroll
                for (int q = 0; q < 16; q++){
                    float4 x = xr[q], wv = wr[q];
                    s0 = fmaf(x.x, wv.x, s0);
                    s1 = fmaf(x.y, wv.y, s1);
                    s2 = fmaf(x.z, wv.z, s2);
                    s3 = fmaf(x.w, wv.w, s3);
                }
            }
            alpha[l0 + li] = (s0 + s1) + (s2 + s3);
        }
    }
    __syncthreads();

    float m = -3.4e38f;
    #pragma unroll
    for (int t8 = 0; t8 < 8; t8++) m = fmaxf(m, alpha[tid + 256 * t8]);
    m = blockMax256(m, red);
    float s = 0.f;
    #pragma unroll
    for (int t8 = 0; t8 < 8; t8++){
        int i = tid + 256 * t8;
        float e = __expf(alpha[i] - m);
        alpha[i] = e;
        s += e;
    }
    s = blockSum256(s, red);
    float invS = __fdividef(1.f, s);

    {
        int d = tid & 127, half = tid >> 7;
        const float* tb = g_tok + (b * LL + half * 1024) * 128 + d;
        float acc = 0.f;
        #pragma unroll 4
        for (int l = 0; l < 1024; l++)
            acc = fmaf(alpha[half * 1024 + l], tb[l * 128], acc);
        float* nhp = Xt;
        nhp[tid] = acc;
        __syncthreads();
        if (tid < 128) nh[tid] = (nhp[tid] + nhp[128 + tid]) * invS;
        __syncthreads();
    }

    const float4* nh4 = (const float4*)nh;
    #pragma unroll 1
    for (int t8 = 0; t8 < 8; t8++){
        int l = t8 * 256 + tid;
        const float4* tr = (const float4*)(g_tok + (b * LL + l) * 128);
        float s0 = 0.f, s1 = 0.f, s2 = 0.f, s3 = 0.f;
        #pragma unroll
        for (int q = 0; q < 32; q++){
            float4 x = tr[q], nn = nh4[q];
            s0 = fmaf(x.x, nn.x, s0);
            s1 = fmaf(x.y, nn.y, s1);
            s2 = fmaf(x.z, nn.z, s2);
            s3 = fmaf(x.w, nn.w, s3);
        }
        int tokid = __ldg(&code[b * LL + l]);
        alpha[l] = (s0 + s1) + (s2 + s3) + __ldg(&bias_tb[tokid]);
    }
    __syncthreads();

    float m2 = -3.4e38f;
    #pragma unroll
    for (int t8 = 0; t8 < 8; t8++) m2 = fmaxf(m2, alpha[tid + 256 * t8]);
    m2 = blockMax256(m2, red);
    float s2s = 0.f;
    #pragma unroll
    for (int t8 = 0; t8 < 8; t8++){
        int i = tid + 256 * t8;
        float e = __expf(alpha[i] - m2);
        alpha[i] = e;
        s2s += e;
    }
    s2s = blockSum256(s2s, red);
    float inv2 = __fdividef(1.f, s2s);
    #pragma unroll
    for (int t8 = 0; t8 < 8; t8++){
        int i = tid + 256 * t8;
        out[b * LL + i] = alpha[i] * inv2;
    }
}

// ---------------- launcher ----------------
extern "C" void kernel_launch(void* const* d_in, const int* in_sizes, int n_in,
                              void* d_out, int out_size){
    const int*   code   = (const int*)  d_in[0];
    const float* E      = (const float*)d_in[1];
    const float* biastb = (const float*)d_in[2];
    const float* Wx     = (const float*)d_in[3];
    const float* Wh     = (const float*)d_in[4];
    const float* bg     = (const float*)d_in[5];
    const float* c1w    = (const float*)d_in[6];
    const float* c1b    = (const float*)d_in[7];
    const float* c2w    = (const float*)d_in[8];
    const float* c2b    = (const float*)d_in[9];
    const float* c3w    = (const float*)d_in[10];
    const float* c3b    = (const float*)d_in[11];
    float* out = (float*)d_out;

    k_gather<<<BB * LL * 32 / 256, 256>>>(code, (const float4*)E);
    k_xproj <<<BB * LL / 64, 256>>>(Wx, bg);
    k_conv1 <<<dim3(LL / 64, BB), 256>>>(c1w, c1b);
    k_gru   <<<BB, 192>>>(Wh, bg);
    k_conv2 <<<dim3(LL / 64, BB), 256>>>(c2w, c2b);
    k_final <<<BB, 256>>>(code, biastb, c3w, c3b, out);
}

// round 6
// speedup vs baseline: 1.4505x; 1.4505x over previous
#include <cuda_runtime.h>
#include <math.h>

#define BB 64
#define LL 2048
#define DD 128
#define KK 64
#define TU 192   // 3*K2

// ---------------- scratch (no cudaMalloc allowed) ----------------
__device__ float g_tok  [BB*LL*DD];   // [B,L,128] gathered embeddings
__device__ float g_xproj[BB*LL*TU];   // [B,L,192] tok@Wx + b0
__device__ float g_L1   [BB*LL*KK];   // conv1+relu
__device__ float g_Lfeat[BB*LL*KK];   // normalized attention features
__device__ float g_hT   [BB*KK];      // GRU final state

// ---------------- helpers ----------------
__device__ __forceinline__ float sigm_f(float x){
    x = fminf(fmaxf(x, -30.f), 30.f);
    return __fdividef(1.f, 1.f + __expf(-x));
}
__device__ __forceinline__ float tanh_f(float x){
    x = fminf(fmaxf(x, -15.f), 15.f);
    float e = __expf(-2.f * x);
    return __fdividef(1.f - e, 1.f + e);
}
__device__ __forceinline__ void cp_async4(unsigned int smem_addr, const float* gptr){
    asm volatile("cp.async.ca.shared.global [%0], [%1], 4;\n"
                 :: "r"(smem_addr), "l"(gptr));
}
__device__ __forceinline__ void cp_commit(){
    asm volatile("cp.async.commit_group;\n" ::: "memory");
}
template<int N>
__device__ __forceinline__ void cp_wait(){
    asm volatile("cp.async.wait_group %0;\n" :: "n"(N) : "memory");
}

// ---------------- k0: gather embeddings ----------------
__global__ void __launch_bounds__(256) k_gather(const int* __restrict__ code,
                                                const float4* __restrict__ E4){
    int i = blockIdx.x * 256 + threadIdx.x;   // over BB*LL*32 float4s
    int token = i >> 5;
    int j = i & 31;
    int row = __ldg(&code[token]);
    ((float4*)g_tok)[i] = E4[row * 32 + j];
}

// ---------------- k1: x_proj = tok @ Wx + b0  (M=B*L, N=192, K=128) ----------------
__global__ void __launch_bounds__(256) k_xproj(const float* __restrict__ Wx,
                                               const float* __restrict__ bg){
    __shared__ __align__(16) float As[64 * 36];
    __shared__ __align__(16) float Bs[32 * 192];
    int tid = threadIdx.x;
    int tx = tid & 15, ty = tid >> 4;
    int r0 = ty * 4;
    int rowbase = blockIdx.x * 64;

    float4 acc[4][3];
    #pragma unroll
    for (int i = 0; i < 4; i++)
        #pragma unroll
        for (int j = 0; j < 3; j++)
            acc[i][j] = make_float4(0.f, 0.f, 0.f, 0.f);

    const float4* tok4 = (const float4*)g_tok;
    const float4* Wx4  = (const float4*)Wx;

    for (int kt = 0; kt < 4; kt++){
        __syncthreads();
        #pragma unroll
        for (int v = 0; v < 2; v++){
            int q = tid + v * 256;
            int row = q >> 3, j = q & 7;
            ((float4*)As)[row * 9 + j] = tok4[(rowbase + row) * 32 + kt * 8 + j];
        }
        #pragma unroll
        for (int v = 0; v < 6; v++){
            int q = tid + v * 256;
            ((float4*)Bs)[q] = Wx4[kt * 1536 + q];
        }
        __syncthreads();
        #pragma unroll
        for (int kk = 0; kk < 32; kk++){
            float a[4];
            #pragma unroll
            for (int i = 0; i < 4; i++) a[i] = As[(r0 + i) * 36 + kk];
            float4 b0 = ((const float4*)Bs)[kk * 48 + tx * 3 + 0];
            float4 b1 = ((const float4*)Bs)[kk * 48 + tx * 3 + 1];
            float4 b2 = ((const float4*)Bs)[kk * 48 + tx * 3 + 2];
            #pragma unroll
            for (int i = 0; i < 4; i++){
                acc[i][0].x = fmaf(a[i], b0.x, acc[i][0].x);
                acc[i][0].y = fmaf(a[i], b0.y, acc[i][0].y);
                acc[i][0].z = fmaf(a[i], b0.z, acc[i][0].z);
                acc[i][0].w = fmaf(a[i], b0.w, acc[i][0].w);
                acc[i][1].x = fmaf(a[i], b1.x, acc[i][1].x);
                acc[i][1].y = fmaf(a[i], b1.y, acc[i][1].y);
                acc[i][1].z = fmaf(a[i], b1.z, acc[i][1].z);
                acc[i][1].w = fmaf(a[i], b1.w, acc[i][1].w);
                acc[i][2].x = fmaf(a[i], b2.x, acc[i][2].x);
                acc[i][2].y = fmaf(a[i], b2.y, acc[i][2].y);
                acc[i][2].z = fmaf(a[i], b2.z, acc[i][2].z);
                acc[i][2].w = fmaf(a[i], b2.w, acc[i][2].w);
            }
        }
    }
    const float4* bg4 = (const float4*)bg;
    #pragma unroll
    for (int i = 0; i < 4; i++){
        int row = rowbase + r0 + i;
        float4* o = ((float4*)g_xproj) + row * 48 + tx * 3;
        #pragma unroll
        for (int j = 0; j < 3; j++){
            float4 bb = bg4[tx * 3 + j];
            float4 v = acc[i][j];
            v.x += bb.x; v.y += bb.y; v.z += bb.z; v.w += bb.w;
            o[j] = v;
        }
    }
}

// ---------------- k2: conv1 (+bias +relu), K = 8*128 ----------------
__global__ void __launch_bounds__(256) k_conv1(const float* __restrict__ w,
                                               const float* __restrict__ bias){
    __shared__ __align__(16) float Xs[71 * 68];
    __shared__ __align__(16) float Ws[64 * 64];
    int b = blockIdx.y;
    int l0 = blockIdx.x * 64;
    int tid = threadIdx.x, tx = tid & 15, ty = tid >> 4;
    int r0 = ty * 4;

    float4 acc[4];
    #pragma unroll
    for (int i = 0; i < 4; i++) acc[i] = make_float4(0.f, 0.f, 0.f, 0.f);

    const float4* src4 = (const float4*)g_tok;

    for (int h = 0; h < 2; h++){
        __syncthreads();
        for (int q = tid; q < 71 * 16; q += 256){
            int row = q >> 4, j = q & 15;
            int l = l0 - 3 + row;
            float4 v = make_float4(0.f, 0.f, 0.f, 0.f);
            if (l >= 0 && l < LL) v = src4[(b * LL + l) * 32 + h * 16 + j];
            ((float4*)Xs)[row * 17 + j] = v;
        }
        for (int ww = 0; ww < 8; ww++){
            __syncthreads();
            const float4* slab4 = (const float4*)(w + (ww * 128 + h * 64) * 64);
            for (int q = tid; q < 1024; q += 256) ((float4*)Ws)[q] = slab4[q];
            __syncthreads();
            #pragma unroll
            for (int ci = 0; ci < 64; ci++){
                float4 bb = ((const float4*)Ws)[ci * 16 + tx];
                float a0 = Xs[(r0 + 0 + ww) * 68 + ci];
                float a1 = Xs[(r0 + 1 + ww) * 68 + ci];
                float a2 = Xs[(r0 + 2 + ww) * 68 + ci];
                float a3 = Xs[(r0 + 3 + ww) * 68 + ci];
                acc[0].x = fmaf(a0, bb.x, acc[0].x); acc[0].y = fmaf(a0, bb.y, acc[0].y);
                acc[0].z = fmaf(a0, bb.z, acc[0].z); acc[0].w = fmaf(a0, bb.w, acc[0].w);
                acc[1].x = fmaf(a1, bb.x, acc[1].x); acc[1].y = fmaf(a1, bb.y, acc[1].y);
                acc[1].z = fmaf(a1, bb.z, acc[1].z); acc[1].w = fmaf(a1, bb.w, acc[1].w);
                acc[2].x = fmaf(a2, bb.x, acc[2].x); acc[2].y = fmaf(a2, bb.y, acc[2].y);
                acc[2].z = fmaf(a2, bb.z, acc[2].z); acc[2].w = fmaf(a2, bb.w, acc[2].w);
                acc[3].x = fmaf(a3, bb.x, acc[3].x); acc[3].y = fmaf(a3, bb.y, acc[3].y);
                acc[3].z = fmaf(a3, bb.z, acc[3].z); acc[3].w = fmaf(a3, bb.w, acc[3].w);
            }
        }
    }
    float4 cbv = ((const float4*)bias)[tx];
    #pragma unroll
    for (int i = 0; i < 4; i++){
        float4 v = acc[i];
        v.x = fmaxf(v.x + cbv.x, 0.f); v.y = fmaxf(v.y + cbv.y, 0.f);
        v.z = fmaxf(v.z + cbv.z, 0.f); v.w = fmaxf(v.w + cbv.w, 0.f);
        ((float4*)g_L1)[(b * LL + l0 + r0 + i) * 16 + tx] = v;
    }
}

// ---------------- k3: GRU scan — scalar FFMA matvec + cp.async 4-step x_proj pipeline ----------------
__global__ void __launch_bounds__(192) k_gru(const float* __restrict__ Wh,
                                             const float* __restrict__ bg){
    int b = blockIdx.x, t = threadIdx.x;        // t in [0,192)
    __shared__ __align__(16) float h_sh[64];
    __shared__ float hp_sh[192];
    __shared__ __align__(16) float xq[5][192];  // x_proj ring buffer

    float wh[64];
    #pragma unroll
    for (int i = 0; i < 64; i++) wh[i] = Wh[i * 192 + t];
    float b1 = bg[192 + t];
    if (t < 64) h_sh[t] = 0.f;

    const float* xb = g_xproj + b * LL * 192;
    unsigned int xq_base = (unsigned int)__cvta_generic_to_shared(&xq[0][0]);

    // prologue: prefetch steps 0..3, one commit group each
    #pragma unroll
    for (int p = 0; p < 4; p++){
        cp_async4(xq_base + (unsigned)(p * 192 + t) * 4u, xb + p * 192 + t);
        cp_commit();
    }
    __syncthreads();

    int rd = 0, wr = 4;   // ring read/write slots
    float hn = 0.f;
    for (int l = 0; l < LL; l++){
        // issue prefetch for step l+4 (empty group if out of range keeps counts aligned)
        int lp = l + 4;
        if (lp < LL) cp_async4(xq_base + (unsigned)(wr * 192 + t) * 4u, xb + lp * 192 + t);
        cp_commit();

        // matvec: hp[t] = Wh[:,t]·h + b1  (all 192 threads)
        float a0 = 0.f, a1 = 0.f, a2 = 0.f, a3 = 0.f;
        #pragma unroll
        for (int i = 0; i < 64; i += 4){
            float4 h4 = *(const float4*)(h_sh + i);
            a0 = fmaf(wh[i + 0], h4.x, a0);
            a1 = fmaf(wh[i + 1], h4.y, a1);
            a2 = fmaf(wh[i + 2], h4.z, a2);
            a3 = fmaf(wh[i + 3], h4.w, a3);
        }
        float hp = (a0 + a1) + (a2 + a3) + b1;
        hp_sh[t] = hp;

        cp_wait<4>();      // group for step l complete (4 still in flight)
        __syncthreads();   // hp_sh + xq[rd] visible block-wide

        if (t < 64){
            const float* xrow = xq[rd];
            float z  = sigm_f(xrow[t]       + hp_sh[t]);
            float r  = sigm_f(xrow[64 + t]  + hp_sh[64 + t]);
            float hh = tanh_f(xrow[128 + t] + r * hp_sh[128 + t]);
            hn = fmaf(z, hn - hh, hh);      // z*h + (1-z)*hh
            h_sh[t] = hn;
        }
        __syncthreads();

        rd = (rd == 4) ? 0 : rd + 1;
        wr = (wr == 4) ? 0 : wr + 1;
    }
    if (t < 64) g_hT[b * 64 + t] = hn;
}

// ---------------- k4: conv2 + bias, * h_T, l2-normalize ----------------
__global__ void __launch_bounds__(256) k_conv2(const float* __restrict__ w,
                                               const float* __restrict__ bias){
    __shared__ __align__(16) float Xs[71 * 68];
    __shared__ __align__(16) float Ws[64 * 64];
    __shared__ float inv[64];
    int b = blockIdx.y;
    int l0 = blockIdx.x * 64;
    int tid = threadIdx.x, tx = tid & 15, ty = tid >> 4;
    int r0 = ty * 4;

    float4 acc[4];
    #pragma unroll
    for (int i = 0; i < 4; i++) acc[i] = make_float4(0.f, 0.f, 0.f, 0.f);

    const float4* src4 = (const float4*)g_L1;
    for (int q = tid; q < 71 * 16; q += 256){
        int row = q >> 4, j = q & 15;
        int l = l0 - 3 + row;
        float4 v = make_float4(0.f, 0.f, 0.f, 0.f);
        if (l >= 0 && l < LL) v = src4[(b * LL + l) * 16 + j];
        ((float4*)Xs)[row * 17 + j] = v;
    }
    for (int ww = 0; ww < 8; ww++){
        __syncthreads();
        const float4* slab4 = (const float4*)(w + ww * 64 * 64);
        for (int q = tid; q < 1024; q += 256) ((float4*)Ws)[q] = slab4[q];
        __syncthreads();
        #pragma unroll
        for (int ci = 0; ci < 64; ci++){
            float4 bb = ((const float4*)Ws)[ci * 16 + tx];
            float a0 = Xs[(r0 + 0 + ww) * 68 + ci];
            float a1 = Xs[(r0 + 1 + ww) * 68 + ci];
            float a2 = Xs[(r0 + 2 + ww) * 68 + ci];
            float a3 = Xs[(r0 + 3 + ww) * 68 + ci];
            acc[0].x = fmaf(a0, bb.x, acc[0].x); acc[0].y = fmaf(a0, bb.y, acc[0].y);
            acc[0].z = fmaf(a0, bb.z, acc[0].z); acc[0].w = fmaf(a0, bb.w, acc[0].w);
            acc[1].x = fmaf(a1, bb.x, acc[1].x); acc[1].y = fmaf(a1, bb.y, acc[1].y);
            acc[1].z = fmaf(a1, bb.z, acc[1].z); acc[1].w = fmaf(a1, bb.w, acc[1].w);
            acc[2].x = fmaf(a2, bb.x, acc[2].x); acc[2].y = fmaf(a2, bb.y, acc[2].y);
            acc[2].z = fmaf(a2, bb.z, acc[2].z); acc[2].w = fmaf(a2, bb.w, acc[2].w);
            acc[3].x = fmaf(a3, bb.x, acc[3].x); acc[3].y = fmaf(a3, bb.y, acc[3].y);
            acc[3].z = fmaf(a3, bb.z, acc[3].z); acc[3].w = fmaf(a3, bb.w, acc[3].w);
        }
    }
    float4 cb = ((const float4*)bias)[tx];
    float4 ht = ((const float4*)g_hT)[b * 16 + tx];
    float4 val[4];
    #pragma unroll
    for (int i = 0; i < 4; i++){
        val[i].x = (acc[i].x + cb.x) * ht.x;
        val[i].y = (acc[i].y + cb.y) * ht.y;
        val[i].z = (acc[i].z + cb.z) * ht.z;
        val[i].w = (acc[i].w + cb.w) * ht.w;
    }
    __syncthreads();
    #pragma unroll
    for (int i = 0; i < 4; i++)
        ((float4*)Xs)[(r0 + i) * 17 + tx] = val[i];
    __syncthreads();
    if (tid < 64){
        float s = 0.f;
        #pragma unroll
        for (int c = 0; c < 64; c++){
            float v = Xs[tid * 68 + c];
            s = fmaf(v, v, s);
        }
        inv[tid] = rsqrtf(s + 1e-12f);
    }
    __syncthreads();
    #pragma unroll
    for (int i = 0; i < 4; i++){
        float iv = inv[r0 + i];
        float4 v = val[i];
        v.x *= iv; v.y *= iv; v.z *= iv; v.w *= iv;
        ((float4*)g_Lfeat)[(b * LL + l0 + r0 + i) * 16 + tx] = v;
    }
}

// ---------------- k5: conv3 -> softmax -> n_hat -> logits -> softmax ----------------
__device__ __forceinline__ float blockMax256(float v, float* red){
    #pragma unroll
    for (int o = 16; o; o >>= 1) v = fmaxf(v, __shfl_xor_sync(0xffffffffu, v, o));
    if ((threadIdx.x & 31) == 0) red[threadIdx.x >> 5] = v;
    __syncthreads();
    if (threadIdx.x < 32){
        float u = (threadIdx.x < 8) ? red[threadIdx.x] : -3.4e38f;
        #pragma unroll
        for (int o = 4; o; o >>= 1) u = fmaxf(u, __shfl_xor_sync(0xffffffffu, u, o));
        if (threadIdx.x == 0) red[0] = u;
    }
    __syncthreads();
    float r = red[0];
    __syncthreads();
    return r;
}
__device__ __forceinline__ float blockSum256(float v, float* red){
    #pragma unroll
    for (int o = 16; o; o >>= 1) v += __shfl_xor_sync(0xffffffffu, v, o);
    if ((threadIdx.x & 31) == 0) red[threadIdx.x >> 5] = v;
    __syncthreads();
    if (threadIdx.x < 32){
        float u = (threadIdx.x < 8) ? red[threadIdx.x] : 0.f;
        #pragma unroll
        for (int o = 4; o; o >>= 1) u += __shfl_xor_sync(0xffffffffu, u, o);
        if (threadIdx.x == 0) red[0] = u;
    }
    __syncthreads();
    float r = red[0];
    __syncthreads();
    return r;
}

__global__ void __launch_bounds__(256) k_final(const int* __restrict__ code,
                                               const float* __restrict__ bias_tb,
                                               const float* __restrict__ c3w,
                                               const float* __restrict__ c3b,
                                               float* __restrict__ out){
    __shared__ __align__(16) float alpha[2048];
    __shared__ __align__(16) float Xt[135 * 68];
    __shared__ __align__(16) float w3s[512];
    __shared__ __align__(16) float nh[128];
    __shared__ float red[32];
    int b = blockIdx.x, tid = threadIdx.x;

    for (int q = tid; q < 512; q += 256) w3s[q] = c3w[q];
    float c3bv = __ldg(c3b);

    const float4* lf4 = (const float4*)g_Lfeat;
    for (int t16 = 0; t16 < 16; t16++){
        int l0 = t16 * 128;
        __syncthreads();
        for (int q = tid; q < 135 * 16; q += 256){
            int row = q >> 4, j = q & 15;
            int l = l0 - 3 + row;
            float4 v = make_float4(0.f, 0.f, 0.f, 0.f);
            if (l >= 0 && l < LL) v = lf4[(b * LL + l) * 16 + j];
            ((float4*)Xt)[row * 17 + j] = v;
        }
        __syncthreads();
        if (tid < 128){
            int li = tid;
            float s0 = c3bv, s1 = 0.f, s2 = 0.f, s3 = 0.f;
            #pragma unroll
            for (int ww = 0; ww < 8; ww++){
                const float4* xr = ((const float4*)Xt) + (li + ww) * 17;
                const float4* wr = ((const float4*)w3s) + ww * 16;
                #pragma unroll
                for (int q = 0; q < 16; q++){
                    float4 x = xr[q], wv = wr[q];
                    s0 = fmaf(x.x, wv.x, s0);
                    s1 = fmaf(x.y, wv.y, s1);
                    s2 = fmaf(x.z, wv.z, s2);
                    s3 = fmaf(x.w, wv.w, s3);
                }
            }
            alpha[l0 + li] = (s0 + s1) + (s2 + s3);
        }
    }
    __syncthreads();

    float m = -3.4e38f;
    #pragma unroll
    for (int t8 = 0; t8 < 8; t8++) m = fmaxf(m, alpha[tid + 256 * t8]);
    m = blockMax256(m, red);
    float s = 0.f;
    #pragma unroll
    for (int t8 = 0; t8 < 8; t8++){
        int i = tid + 256 * t8;
        float e = __expf(alpha[i] - m);
        alpha[i] = e;
        s += e;
    }
    s = blockSum256(s, red);
    float invS = __fdividef(1.f, s);

    {
        int d = tid & 127, half = tid >> 7;
        const float* tb = g_tok + (b * LL + half * 1024) * 128 + d;
        float acc = 0.f;
        #pragma unroll 4
        for (int l = 0; l < 1024; l++)
            acc = fmaf(alpha[half * 1024 + l], tb[l * 128], acc);
        float* nhp = Xt;
        nhp[tid] = acc;
        __syncthreads();
        if (tid < 128) nh[tid] = (nhp[tid] + nhp[128 + tid]) * invS;
        __syncthreads();
    }

    const float4* nh4 = (const float4*)nh;
    #pragma unroll 1
    for (int t8 = 0; t8 < 8; t8++){
        int l = t8 * 256 + tid;
        const float4* tr = (const float4*)(g_tok + (b * LL + l) * 128);
        float s0 = 0.f, s1 = 0.f, s2 = 0.f, s3 = 0.f;
        #pragma unroll
        for (int q = 0; q < 32; q++){
            float4 x = tr[q], nn = nh4[q];
            s0 = fmaf(x.x, nn.x, s0);
            s1 = fmaf(x.y, nn.y, s1);
            s2 = fmaf(x.z, nn.z, s2);
            s3 = fmaf(x.w, nn.w, s3);
        }
        int tokid = __ldg(&code[b * LL + l]);
        alpha[l] = (s0 + s1) + (s2 + s3) + __ldg(&bias_tb[tokid]);
    }
    __syncthreads();

    float m2 = -3.4e38f;
    #pragma unroll
    for (int t8 = 0; t8 < 8; t8++) m2 = fmaxf(m2, alpha[tid + 256 * t8]);
    m2 = blockMax256(m2, red);
    float s2s = 0.f;
    #pragma unroll
    for (int t8 = 0; t8 < 8; t8++){
        int i = tid + 256 * t8;
        float e = __expf(alpha[i] - m2);
        alpha[i] = e;
        s2s += e;
    }
    s2s = blockSum256(s2s, red);
    float inv2 = __fdividef(1.f, s2s);
    #pragma unroll
    for (int t8 = 0; t8 < 8; t8++){
        int i = tid + 256 * t8;
        out[b * LL + i] = alpha[i] * inv2;
    }
}

// ---------------- launcher ----------------
extern "C" void kernel_launch(void* const* d_in, const int* in_sizes, int n_in,
                              void* d_out, int out_size){
    const int*   code   = (const int*)  d_in[0];
    const float* E      = (const float*)d_in[1];
    const float* biastb = (const float*)d_in[2];
    const float* Wx     = (const float*)d_in[3];
    const float* Wh     = (const float*)d_in[4];
    const float* bg     = (const float*)d_in[5];
    const float* c1w    = (const float*)d_in[6];
    const float* c1b    = (const float*)d_in[7];
    const float* c2w    = (const float*)d_in[8];
    const float* c2b    = (const float*)d_in[9];
    const float* c3w    = (const float*)d_in[10];
    const float* c3b    = (const float*)d_in[11];
    float* out = (float*)d_out;

    k_gather<<<BB * LL * 32 / 256, 256>>>(code, (const float4*)E);
    k_xproj <<<BB * LL / 64, 256>>>(Wx, bg);
    k_conv1 <<<dim3(LL / 64, BB), 256>>>(c1w, c1b);
    k_gru   <<<BB, 192>>>(Wh, bg);
    k_conv2 <<<dim3(LL / 64, BB), 256>>>(c2w, c2b);
    k_final <<<BB, 256>>>(code, biastb, c3w, c3b, out);
}